// round 1
// baseline (speedup 1.0000x reference)
#include <cuda_runtime.h>
#include <cuda_bf16.h>
#include <math.h>
#include <stdint.h>

// Problem constants
#define TT 2048          // tokens = B*S
#define HH 2048          // hidden
#define II 1792          // intermediate
#define EE 16            // experts
#define TOPK 4
#define RR (TT*TOPK)     // 8192 gathered rows

// ---------------- scratch (device globals; no allocation) ----------------
__device__ float d_G[(size_t)RR * II];     // gate output, then ACT (in-place)
__device__ float d_U[(size_t)RR * II];     // up output
__device__ float d_Y[(size_t)RR * HH];     // down output per gathered row
__device__ int   d_counts[EE];
__device__ int   d_offsets[EE];
__device__ int   d_cursors[EE];
__device__ int   d_rows[RR];               // pos -> token
__device__ int   d_posof[TT * TOPK];       // (token,k) -> pos
__device__ float d_topw[TT * TOPK];
__device__ int   d_topi[TT * TOPK];

// ---------------- router ----------------
__global__ void zero_counts_kernel() {
    if (threadIdx.x < EE) d_counts[threadIdx.x] = 0;
}

__global__ void router_kernel(const float* __restrict__ x,
                              const float* __restrict__ rw,
                              const float* __restrict__ bias) {
    int warp = (blockIdx.x * blockDim.x + threadIdx.x) >> 5;
    int lane = threadIdx.x & 31;
    if (warp >= TT) return;
    const float* xr = x + (size_t)warp * HH;
    float acc[EE];
#pragma unroll
    for (int e = 0; e < EE; e++) acc[e] = 0.f;
    for (int h = lane; h < HH; h += 32) {
        float xv = __ldg(xr + h);
#pragma unroll
        for (int e = 0; e < EE; e++) acc[e] += xv * __ldg(rw + (size_t)e * HH + h);
    }
#pragma unroll
    for (int e = 0; e < EE; e++) {
        float v = acc[e];
#pragma unroll
        for (int o = 16; o > 0; o >>= 1) v += __shfl_xor_sync(0xffffffffu, v, o);
        acc[e] = v + bias[e];
    }
    if (lane == 0) {
        int idx[TOPK]; float lg[TOPK];
        unsigned used = 0;
        for (int k = 0; k < TOPK; k++) {
            float best = -INFINITY; int bi = 0;
            for (int e = 0; e < EE; e++) {
                if ((used >> e) & 1u) continue;
                if (acc[e] > best) { best = acc[e]; bi = e; }
            }
            used |= 1u << bi; idx[k] = bi; lg[k] = best;
        }
        // softmax over selected logits == softmax-all -> topk -> renorm
        float mx = lg[0];
        float w[TOPK], s = 0.f;
        for (int k = 0; k < TOPK; k++) { w[k] = expf(lg[k] - mx); s += w[k]; }
        float inv = 1.f / s;
        for (int k = 0; k < TOPK; k++) {
            d_topi[warp * TOPK + k] = idx[k];
            d_topw[warp * TOPK + k] = w[k] * inv;
            atomicAdd(&d_counts[idx[k]], 1);
        }
    }
}

__global__ void scan_kernel() {
    int off = 0;
    for (int e = 0; e < EE; e++) {
        d_offsets[e] = off; d_cursors[e] = off; off += d_counts[e];
    }
}

__global__ void assign_kernel() {
    int t = blockIdx.x * blockDim.x + threadIdx.x;
    if (t >= TT) return;
    for (int k = 0; k < TOPK; k++) {
        int e = d_topi[t * TOPK + k];
        int pos = atomicAdd(&d_cursors[e], 1);
        d_rows[pos] = t;
        d_posof[t * TOPK + k] = pos;
    }
}

// ---------------- GEMM (bf16 2-way split, 3 MMAs ~ fp32 precision) ----------------
#define BM 128
#define BN 64
#define BK 32
#define LDK 40   // BK + 8 pad (bf16 elems), 80B rows, 16B aligned
#define LDN 72   // BN + 8 pad, 144B rows, 16B aligned

__device__ __forceinline__ uint32_t smem_u32(const void* p) {
    return (uint32_t)__cvta_generic_to_shared(p);
}
__device__ __forceinline__ void ldsm_x4(uint32_t* r, uint32_t addr) {
    asm volatile("ldmatrix.sync.aligned.m8n8.x4.shared.b16 {%0,%1,%2,%3}, [%4];"
                 : "=r"(r[0]), "=r"(r[1]), "=r"(r[2]), "=r"(r[3]) : "r"(addr));
}
__device__ __forceinline__ void ldsm_x2t(uint32_t* r, uint32_t addr) {
    asm volatile("ldmatrix.sync.aligned.m8n8.x2.trans.shared.b16 {%0,%1}, [%2];"
                 : "=r"(r[0]), "=r"(r[1]) : "r"(addr));
}
__device__ __forceinline__ void mma_bf16(float* d, const uint32_t* a, const uint32_t* b) {
    asm volatile("mma.sync.aligned.m16n8k16.row.col.f32.bf16.bf16.f32 "
                 "{%0,%1,%2,%3}, {%4,%5,%6,%7}, {%8,%9}, {%0,%1,%2,%3};"
                 : "+f"(d[0]), "+f"(d[1]), "+f"(d[2]), "+f"(d[3])
                 : "r"(a[0]), "r"(a[1]), "r"(a[2]), "r"(a[3]), "r"(b[0]), "r"(b[1]));
}

// mode 0: A=x (gather), C=d_G    Kd=HH Nd=II  (gate)
// mode 1: A=x (gather), C=d_U    Kd=HH Nd=II  (up)
// mode 2: A=d_G (direct), C=d_Y  Kd=II Nd=HH  (down)
__global__ __launch_bounds__(256, 2)
void gemm_split_kernel(const float* __restrict__ Aext,
                       const float* __restrict__ Bw,
                       int Kd, int Nd, int mode)
{
    __shared__ __align__(16) __nv_bfloat16 As_hi[BM * LDK];
    __shared__ __align__(16) __nv_bfloat16 As_lo[BM * LDK];
    __shared__ __align__(16) __nv_bfloat16 Bs_hi[BK * LDN];
    __shared__ __align__(16) __nv_bfloat16 Bs_lo[BK * LDN];

    int e = blockIdx.z;
    int cnt = d_counts[e];
    int mblk = blockIdx.y;
    if (mblk * BM >= cnt) return;
    int off = d_offsets[e];
    int nb  = blockIdx.x * BN;

    const float* A = (mode == 2) ? d_G : Aext;
    float* C = (mode == 0) ? d_G : (mode == 1) ? d_U : d_Y;
    const int useGather = (mode < 2);
    const float* Bexp = Bw + (size_t)e * Kd * Nd;

    int tid = threadIdx.x;
    // A loader: each thread loads 4 rows x float4 along k
    int a_r = tid >> 3;            // 0..31
    int a_k = (tid & 7) << 2;      // 0,4,...,28
    bool a_valid[4];
    const float* a_ptr[4];
#pragma unroll
    for (int i = 0; i < 4; i++) {
        int gm = mblk * BM + a_r + 32 * i;
        bool v = gm < cnt;
        a_valid[i] = v;
        int arow = 0;
        if (v) {
            int gpos = off + gm;
            arow = useGather ? d_rows[gpos] : gpos;
        }
        a_ptr[i] = A + (size_t)arow * Kd + a_k;
    }
    // B loader: coalesced copy of K-major weights (no smem transpose; ldmatrix.trans)
    int b_k = tid >> 4;            // 0..15
    int b_n = (tid & 15) << 2;     // 0..60
    const float* b_ptr = Bexp + (size_t)b_k * Nd + nb + b_n;

    int warp = tid >> 5, lane = tid & 31;
    int wm = warp & 3, wn = warp >> 2;                 // 4x2 warps -> 32x32 warp tile
    int sub = lane >> 3, lr = lane & 7;
    int a_row0 = wm * 32 + ((sub & 1) << 3) + lr;      // + am*16
    int a_kc   = (sub >> 1) << 3;                      // + ck*16
    int b_krow = (((lane >> 3) & 1) << 3) + lr;        // + ck*16
    int b_nc0  = wn * 32;                              // + an*8

    float acc[2][4][4];
#pragma unroll
    for (int i = 0; i < 2; i++)
#pragma unroll
        for (int j = 0; j < 4; j++)
#pragma unroll
            for (int c = 0; c < 4; c++) acc[i][j][c] = 0.f;

    float4 a_regs[4];
    float4 b_regs[2];

    auto store_sm = [&]() {
#pragma unroll
        for (int i = 0; i < 4; i++) {
            int lm = a_r + 32 * i;
            float v[4] = {a_regs[i].x, a_regs[i].y, a_regs[i].z, a_regs[i].w};
            __nv_bfloat16 h[4], l[4];
#pragma unroll
            for (int c = 0; c < 4; c++) {
                __nv_bfloat16 hb = __float2bfloat16(v[c]);
                h[c] = hb;
                l[c] = __float2bfloat16(v[c] - __bfloat162float(hb));
            }
            *(__nv_bfloat162*)&As_hi[lm * LDK + a_k]     = __halves2bfloat162(h[0], h[1]);
            *(__nv_bfloat162*)&As_hi[lm * LDK + a_k + 2] = __halves2bfloat162(h[2], h[3]);
            *(__nv_bfloat162*)&As_lo[lm * LDK + a_k]     = __halves2bfloat162(l[0], l[1]);
            *(__nv_bfloat162*)&As_lo[lm * LDK + a_k + 2] = __halves2bfloat162(l[2], l[3]);
        }
#pragma unroll
        for (int j = 0; j < 2; j++) {
            int kk = b_k + 16 * j;
            float v[4] = {b_regs[j].x, b_regs[j].y, b_regs[j].z, b_regs[j].w};
            __nv_bfloat16 h[4], l[4];
#pragma unroll
            for (int c = 0; c < 4; c++) {
                __nv_bfloat16 hb = __float2bfloat16(v[c]);
                h[c] = hb;
                l[c] = __float2bfloat16(v[c] - __bfloat162float(hb));
            }
            *(__nv_bfloat162*)&Bs_hi[kk * LDN + b_n]     = __halves2bfloat162(h[0], h[1]);
            *(__nv_bfloat162*)&Bs_hi[kk * LDN + b_n + 2] = __halves2bfloat162(h[2], h[3]);
            *(__nv_bfloat162*)&Bs_lo[kk * LDN + b_n]     = __halves2bfloat162(l[0], l[1]);
            *(__nv_bfloat162*)&Bs_lo[kk * LDN + b_n + 2] = __halves2bfloat162(l[2], l[3]);
        }
    };

    auto compute = [&]() {
#pragma unroll
        for (int ck = 0; ck < 2; ck++) {
            uint32_t ah[2][4], al[2][4];
#pragma unroll
            for (int am = 0; am < 2; am++) {
                int row = a_row0 + am * 16;
                int col = ck * 16 + a_kc;
                ldsm_x4(ah[am], smem_u32(&As_hi[row * LDK + col]));
                ldsm_x4(al[am], smem_u32(&As_lo[row * LDK + col]));
            }
            uint32_t bh[4][2], bl[4][2];
#pragma unroll
            for (int an = 0; an < 4; an++) {
                int krow = ck * 16 + b_krow;
                int ncol = b_nc0 + an * 8;
                ldsm_x2t(bh[an], smem_u32(&Bs_hi[krow * LDN + ncol]));
                ldsm_x2t(bl[an], smem_u32(&Bs_lo[krow * LDN + ncol]));
            }
#pragma unroll
            for (int am = 0; am < 2; am++)
#pragma unroll
                for (int an = 0; an < 4; an++) {
                    mma_bf16(acc[am][an], ah[am], bh[an]);   // hi*hi
                    mma_bf16(acc[am][an], ah[am], bl[an]);   // hi*lo
                    mma_bf16(acc[am][an], al[am], bh[an]);   // lo*hi
                }
        }
    };

    int NK = Kd / BK;
    // prologue: tile 0
#pragma unroll
    for (int i = 0; i < 4; i++)
        a_regs[i] = a_valid[i] ? *(const float4*)(a_ptr[i]) : make_float4(0, 0, 0, 0);
#pragma unroll
    for (int j = 0; j < 2; j++)
        b_regs[j] = *(const float4*)(b_ptr + (size_t)(j * 16) * Nd);
    store_sm();
    __syncthreads();

    for (int kb = 1; kb < NK; kb++) {
        // prefetch next tile into registers (overlaps with MMA below)
#pragma unroll
        for (int i = 0; i < 4; i++)
            a_regs[i] = a_valid[i] ? *(const float4*)(a_ptr[i] + kb * BK) : make_float4(0, 0, 0, 0);
#pragma unroll
        for (int j = 0; j < 2; j++)
            b_regs[j] = *(const float4*)(b_ptr + (size_t)(kb * BK + j * 16) * Nd);
        compute();
        __syncthreads();
        store_sm();
        __syncthreads();
    }
    compute();

    // epilogue
    int lrow = lane >> 2;
    int lcol = (lane & 3) << 1;
#pragma unroll
    for (int am = 0; am < 2; am++) {
#pragma unroll
        for (int hf = 0; hf < 2; hf++) {
            int row = wm * 32 + am * 16 + hf * 8 + lrow;
            int gm = mblk * BM + row;
            if (gm < cnt) {
                size_t base = (size_t)(off + gm) * Nd + nb + wn * 32 + lcol;
#pragma unroll
                for (int an = 0; an < 4; an++) {
                    float2 val = make_float2(acc[am][an][hf * 2], acc[am][an][hf * 2 + 1]);
                    *(float2*)&C[base + an * 8] = val;
                }
            }
        }
    }
}

// ---------------- elementwise SwiGLU: ACT = silu(G)*U (into G) ----------------
__global__ void silu_mul_kernel() {
    size_t i = ((size_t)blockIdx.x * blockDim.x + threadIdx.x) * 4;
    if (i >= (size_t)RR * II) return;
    float4 g = *(float4*)&d_G[i];
    float4 u = *(float4*)&d_U[i];
    g.x = g.x / (1.f + expf(-g.x)) * u.x;
    g.y = g.y / (1.f + expf(-g.y)) * u.y;
    g.z = g.z / (1.f + expf(-g.z)) * u.z;
    g.w = g.w / (1.f + expf(-g.w)) * u.w;
    *(float4*)&d_G[i] = g;
}

// ---------------- combine: out[t] = sum_k w_k * Y[pos_k] (deterministic) ----------------
__global__ void combine_kernel(float* __restrict__ out) {
    int t = blockIdx.x;
    float w[TOPK]; int p[TOPK];
#pragma unroll
    for (int k = 0; k < TOPK; k++) {
        w[k] = d_topw[t * TOPK + k];
        p[k] = d_posof[t * TOPK + k];
    }
    for (int h = threadIdx.x * 4; h < HH; h += blockDim.x * 4) {
        float4 s = make_float4(0, 0, 0, 0);
#pragma unroll
        for (int k = 0; k < TOPK; k++) {
            float4 y = *(const float4*)&d_Y[(size_t)p[k] * HH + h];
            s.x += w[k] * y.x; s.y += w[k] * y.y;
            s.z += w[k] * y.z; s.w += w[k] * y.w;
        }
        *(float4*)&out[(size_t)t * HH + h] = s;
    }
}

// ---------------- launch ----------------
extern "C" void kernel_launch(void* const* d_in, const int* in_sizes, int n_in,
                              void* d_out, int out_size) {
    const float* x    = (const float*)d_in[0];
    const float* rw   = (const float*)d_in[1];
    const float* bias = (const float*)d_in[2];
    const float* gate = (const float*)d_in[3];
    const float* up   = (const float*)d_in[4];
    const float* down = (const float*)d_in[5];
    float* out = (float*)d_out;

    zero_counts_kernel<<<1, 32>>>();
    router_kernel<<<TT / 8, 256>>>(x, rw, bias);     // warp per token
    scan_kernel<<<1, 1>>>();
    assign_kernel<<<TT / 256, 256>>>();

    dim3 g_gu(II / BN, TT / BM, EE);                 // 28 x 16 x 16 (inactive m-tiles early-exit)
    gemm_split_kernel<<<g_gu, 256>>>(x, gate, HH, II, 0);
    gemm_split_kernel<<<g_gu, 256>>>(x, up,   HH, II, 1);

    silu_mul_kernel<<<((size_t)RR * II / 4 + 255) / 256, 256>>>();

    dim3 g_d(HH / BN, TT / BM, EE);                  // 32 x 16 x 16
    gemm_split_kernel<<<g_d, 256>>>(nullptr, down, II, HH, 2);

    combine_kernel<<<TT, 256>>>(out);
}